// round 17
// baseline (speedup 1.0000x reference)
#include <cuda_runtime.h>
#include <cuda_bf16.h>

// out shape (1, 8, 4096, 4096) fp32, 512 MiB of stores.
// c in 0..3:  out[c][i][j] = table[seq[i]*4 + c]      (row splat, constant over j)
// c in 4..7:  out[c][i][j] = table[seq[j]*4 + (c-4)]  (identical 16KB pattern every i)
//
// R1 structure (one 16KB row per block, 256 threads) with Blackwell 256-bit
// streaming stores (st.global.cs.v8.f32): 2 stores/thread instead of 4,
// halving STG instruction + L1tex wavefront count per byte.

#define L 4096
#define NB 4

__device__ __forceinline__ void stcs_v8(float* p, const float v[8])
{
    asm volatile("st.global.cs.v8.f32 [%0], {%1,%2,%3,%4,%5,%6,%7,%8};"
                 :: "l"(p),
                    "f"(v[0]), "f"(v[1]), "f"(v[2]), "f"(v[3]),
                    "f"(v[4]), "f"(v[5]), "f"(v[6]), "f"(v[7])
                 : "memory");
}

__global__ __launch_bounds__(256, 8)
void seq_embed_kernel(const int* __restrict__ seq,
                      const float* __restrict__ table,
                      float* __restrict__ out)
{
    const int i = blockIdx.x;   // 0..4095
    const int c = blockIdx.y;   // 0..7
    const int t = threadIdx.x;

    __shared__ float tbl[NB * NB];
    if (t < NB * NB) tbl[t] = table[t];
    __syncthreads();

    float* row = out + (((size_t)c * L) + (size_t)i) * (size_t)L;

    if (c < NB) {
        // splat row: constant value across j
        const float v = tbl[seq[i] * NB + c];
        float v8[8] = {v, v, v, v, v, v, v, v};
#pragma unroll
        for (int k = 0; k < 2; ++k) {
            const int slot = t + 256 * k;          // v8 slot (32B), coalesced
            stcs_v8(row + slot * 8, v8);
        }
    } else {
        const int cc = c - NB;
        const int4* seq4 = reinterpret_cast<const int4*>(seq);
        // front-batch 4 gathers (16KB seq is L1-resident)
        int4 s[4];
#pragma unroll
        for (int q = 0; q < 4; ++q) {
            const int slot = t + 256 * (q >> 1);   // two int4 per v8 slot
            s[q] = __ldg(seq4 + slot * 2 + (q & 1));
        }
#pragma unroll
        for (int k = 0; k < 2; ++k) {
            float v8[8];
            const int4 a = s[2 * k + 0];
            const int4 b = s[2 * k + 1];
            v8[0] = tbl[a.x * NB + cc];
            v8[1] = tbl[a.y * NB + cc];
            v8[2] = tbl[a.z * NB + cc];
            v8[3] = tbl[a.w * NB + cc];
            v8[4] = tbl[b.x * NB + cc];
            v8[5] = tbl[b.y * NB + cc];
            v8[6] = tbl[b.z * NB + cc];
            v8[7] = tbl[b.w * NB + cc];
            const int slot = t + 256 * k;
            stcs_v8(row + slot * 8, v8);
        }
    }
}

extern "C" void kernel_launch(void* const* d_in, const int* in_sizes, int n_in,
                              void* d_out, int out_size)
{
    const int*   seq   = (const int*)d_in[0];    // seq_ids (int32)
    const float* table = (const float*)d_in[1];  // base_table (4x4)
    float*       out   = (float*)d_out;          // (1, 8, 4096, 4096) fp32

    dim3 grid(L, 2 * NB);
    seq_embed_kernel<<<grid, 256>>>(seq, table, out);
}